// round 4
// baseline (speedup 1.0000x reference)
#include <cuda_runtime.h>
#include <cstdlib>

// Problem: H=16, T=128, S=128, C=257, TP=8
// ct_val[t,s,c,p] = (sum_q d_sta[t,s,q] - d_sta[t,s,p] + d_cnc[t,s,c,p]) / TP
// d(c1,c2,norm) = sgn(c1)sgn(c2) * (1 - (32-clz(|c1|^|c2|+1))/16) * norm
// Output fp32 (T,S,C,TP) = 134.7 MB

#define TT 128
#define SS 128
#define CC 257
#define TP 8
#define SCH 16                 // s-values per block
#define NBLK (TT * (SS / SCH)) // 1024

__global__ __launch_bounds__(256, 6)
void critigraph_kernel(const int*   __restrict__ sta,
                       const int*   __restrict__ pos,
                       const int*   __restrict__ cnc,
                       const float* __restrict__ eu,
                       float*       __restrict__ out)
{
    const int t   = blockIdx.x >> 3;          // S/SCH = 8 chunks per t
    const int s0  = (blockIdx.x & 7) * SCH;
    const int tid = threadIdx.x;

    // per-s scalars, vector-load friendly layout (16B aligned rows)
    __shared__ float sh_base[SCH][TP];   // (sum - d_sta[p]) / TP
    __shared__ float sh_fscl[SCH][TP];   // sgn(pos) * norm / TP
    __shared__ int   sh_pabs[SCH][TP];   // |pos|

    // ---- Phase 1: per-(t,s) scalars for 16 s values (threads 0..127) -----
    if (tid < SCH * TP) {
        const int i = tid >> 3;          // s index within chunk
        const int p = tid & 7;
        const int   sv   = sta[t * TP + p];
        const int   pv   = pos[(size_t)(t * SS + s0) * TP + tid]; // contiguous
        const float norm = eu[t * SS + s0 + i];

        const int x = (abs(sv) ^ abs(pv)) + 1;                 // [1, 65536]
        float f = fmaf((float)(32 - __clz(x)), -0.0625f, 1.0f);
        float d = ((sv ^ pv) < 0) ? -f * norm : f * norm;

        // butterfly sum over the 8-lane p-group (stays inside the group)
        float sum = d;
        #pragma unroll
        for (int m = 1; m < TP; m <<= 1)
            sum += __shfl_xor_sync(0xffffffffu, sum, m);

        sh_base[i][p] = (sum - d) * 0.125f;
        sh_pabs[i][p] = abs(pv);
        sh_fscl[i][p] = ((pv >= 0) ? norm : -norm) * 0.125f;
    }
    __syncthreads();

    // ---- Phase 2: candidates resident in registers, loop over s ----------
    // c = tid (+ second pass c=256 for thread 0 only)
    for (int c = tid; c < CC; c += 256) {
        const int4* cp = reinterpret_cast<const int4*>(cnc + ((size_t)t * CC + c) * TP);
        const int4 a = __ldg(cp);
        const int4 b = __ldg(cp + 1);
        const int cv[TP] = {a.x, a.y, a.z, a.w, b.x, b.y, b.z, b.w};
        int cpk[TP];   // |c| in low 16 bits, sign of c in bit 31
        #pragma unroll
        for (int p = 0; p < TP; ++p)
            cpk[p] = abs(cv[p]) | (cv[p] & 0x80000000);

        float* op = out + ((size_t)(t * SS + s0) * CC + c) * TP;

        #pragma unroll 4
        for (int i = 0; i < SCH; ++i) {
            const float4 b0 = *reinterpret_cast<const float4*>(&sh_base[i][0]);
            const float4 f0 = *reinterpret_cast<const float4*>(&sh_fscl[i][0]);
            const int4   q0 = *reinterpret_cast<const int4*>(&sh_pabs[i][0]);
            float4 r0;
            {
                const int qq[4] = {q0.x, q0.y, q0.z, q0.w};
                const float bb[4] = {b0.x, b0.y, b0.z, b0.w};
                const float ff[4] = {f0.x, f0.y, f0.z, f0.w};
                float rr[4];
                #pragma unroll
                for (int p = 0; p < 4; ++p) {
                    const int x = ((cpk[p] ^ qq[p]) & 0xFFFF) + 1;
                    float f = fmaf((float)(32 - __clz(x)), -0.0625f, 1.0f);
                    // negate iff candidate negative (sign-bit XOR == negation)
                    f = __int_as_float(__float_as_int(f) ^ (cpk[p] & 0x80000000));
                    rr[p] = fmaf(f, ff[p], bb[p]);
                }
                r0 = make_float4(rr[0], rr[1], rr[2], rr[3]);
            }
            *reinterpret_cast<float4*>(op) = r0;

            const float4 b1 = *reinterpret_cast<const float4*>(&sh_base[i][4]);
            const float4 f1 = *reinterpret_cast<const float4*>(&sh_fscl[i][4]);
            const int4   q1 = *reinterpret_cast<const int4*>(&sh_pabs[i][4]);
            float4 r1;
            {
                const int qq[4] = {q1.x, q1.y, q1.z, q1.w};
                const float bb[4] = {b1.x, b1.y, b1.z, b1.w};
                const float ff[4] = {f1.x, f1.y, f1.z, f1.w};
                float rr[4];
                #pragma unroll
                for (int p = 0; p < 4; ++p) {
                    const int x = ((cpk[p + 4] ^ qq[p]) & 0xFFFF) + 1;
                    float f = fmaf((float)(32 - __clz(x)), -0.0625f, 1.0f);
                    f = __int_as_float(__float_as_int(f) ^ (cpk[p + 4] & 0x80000000));
                    rr[p] = fmaf(f, ff[p], bb[p]);
                }
                r1 = make_float4(rr[0], rr[1], rr[2], rr[3]);
            }
            *reinterpret_cast<float4*>(op + 4) = r1;

            op += (size_t)CC * TP;   // next s row
        }
    }
}

extern "C" void kernel_launch(void* const* d_in, const int* in_sizes, int n_in,
                              void* d_out, int out_size)
{
    const int*   sta = (const int*)d_in[0];
    const int*   pos = (const int*)d_in[1];
    const int*   cnc = (const int*)d_in[2];
    const float* eu  = (const float*)d_in[3];
    float*       out = (float*)d_out;

    critigraph_kernel<<<NBLK, 256>>>(sta, pos, cnc, eu, out);
}